// round 1
// baseline (speedup 1.0000x reference)
#include <cuda_runtime.h>

#define FULLMASK 0xffffffffu
static constexpr float EPSF    = 1e-8f;
static constexpr float INV2PI  = 0.15915494309189535f;

// sin(2*pi*x) via range reduction to r in [-0.5,0.5] and odd deg-13 Taylor.
// Max abs error ~2.2e-5 over the full range — far inside the 1e-3 budget.
__device__ __forceinline__ float sin2pi(float x) {
    float r = x - rintf(x);          // [-0.5, 0.5]
    float z = r * r;
    float p =              3.8199526e0f;   // +(2pi)^13/13!
    p = fmaf(p, z, -1.5094643e1f);         // -(2pi)^11/11!
    p = fmaf(p, z,  4.2058693e1f);         // +(2pi)^9 / 9!
    p = fmaf(p, z, -7.6705859e1f);         // -(2pi)^7 / 7!
    p = fmaf(p, z,  8.1605249e1f);         // +(2pi)^5 / 5!
    p = fmaf(p, z, -4.1341702e1f);         // -(2pi)^3 / 3!
    p = fmaf(p, z,  6.2831853e0f);         // +(2pi)
    return p * r;
}

__device__ __forceinline__ float diff_round(float x) {
    return fmaf(sin2pi(x), -INV2PI, x);
}

__global__ void zero_out_kernel(float* out, int n) {
    int i = blockIdx.x * blockDim.x + threadIdx.x;
    if (i < n) out[i] = 0.0f;
}

// One warp per area (64 floats = 32 lanes x float2).
__global__ __launch_bounds__(256) void area_loss_kernel(
    const float* __restrict__ img,
    const float* __restrict__ msk,
    float* __restrict__ out,
    int nAreas, float invTotal)
{
    __shared__ float bsum;
    if (threadIdx.x == 0) bsum = 0.0f;
    __syncthreads();

    const int lane   = threadIdx.x & 31;
    const int warpId = (blockIdx.x * blockDim.x + threadIdx.x) >> 5;
    const int nWarps = (gridDim.x * blockDim.x) >> 5;

    const float2* __restrict__ img2 = reinterpret_cast<const float2*>(img);
    const float2* __restrict__ msk2 = reinterpret_cast<const float2*>(msk);

    float acc = 0.0f;

    for (int a = warpId; a < nAreas; a += nWarps) {
        const int base = a * 32 + lane;
        float2 iv = img2[base];
        float2 mv = msk2[base];

        float m0 = diff_round(diff_round(mv.x));
        float m1 = diff_round(diff_round(mv.y));
        float t0 = iv.x * m0;
        float t1 = iv.y * m1;

        float sm = m0 + m1;
        float si = t0 + t1;
        #pragma unroll
        for (int o = 16; o > 0; o >>= 1) {
            sm += __shfl_xor_sync(FULLMASK, sm, o);
            si += __shfl_xor_sync(FULLMASK, si, o);
        }

        float msum = sm + EPSF;
        float rinv = __frcp_rn(msum);
        float mean = si * rinv;

        float d0 = (t0 - mean) * m0;
        float d1 = (t1 - mean) * m1;
        float sv = fmaf(d0, d0, d1 * d1);
        #pragma unroll
        for (int o = 16; o > 0; o >>= 1) {
            sv += __shfl_xor_sync(FULLMASK, sv, o);
        }

        acc = fmaf(sv, rinv, acc);   // all lanes hold identical sv, rinv
    }

    // one add per warp into shared, one global atomic per block
    if (lane == 0) atomicAdd(&bsum, acc);
    __syncthreads();
    if (threadIdx.x == 0) atomicAdd(out, bsum * invTotal);
}

extern "C" void kernel_launch(void* const* d_in, const int* in_sizes, int n_in,
                              void* d_out, int out_size)
{
    const float* img = (const float*)d_in[0];   // sv_area_image
    const float* msk = (const float*)d_in[1];   // sv_area_mask
    float* out = (float*)d_out;

    const int nAreas = in_sizes[0] / 64;        // B*N areas of 8x8
    const float invTotal = 1.0f / (float)nAreas;

    zero_out_kernel<<<(out_size + 255) / 256, 256>>>(out, out_size);

    const int threads = 256;
    const int blocks  = 1024;                   // 8192 warps -> 16 areas/warp
    area_loss_kernel<<<blocks, threads>>>(img, msk, out, nAreas, invTotal);
}

// round 4
// speedup vs baseline: 1.3624x; 1.3624x over previous
#include <cuda_runtime.h>

typedef unsigned long long u64;
#define FULLMASK 0xffffffffu
static constexpr float EPSF = 1e-8f;

// ---------- packed f32x2 helpers (sm_103a) ----------
__device__ __forceinline__ u64 pk2(float lo, float hi) {
    u64 d; asm("mov.b64 %0,{%1,%2};" : "=l"(d) : "f"(lo), "f"(hi)); return d;
}
__device__ __forceinline__ float2 upk2(u64 v) {
    float2 o; asm("mov.b64 {%0,%1},%2;" : "=f"(o.x), "=f"(o.y) : "l"(v)); return o;
}
__device__ __forceinline__ u64 fma2_(u64 a, u64 b, u64 c) {
    u64 d; asm("fma.rn.f32x2 %0,%1,%2,%3;" : "=l"(d) : "l"(a), "l"(b), "l"(c)); return d;
}
__device__ __forceinline__ u64 mul2_(u64 a, u64 b) {
    u64 d; asm("mul.rn.f32x2 %0,%1,%2;" : "=l"(d) : "l"(a), "l"(b)); return d;
}
__device__ __forceinline__ u64 add2_(u64 a, u64 b) {
    u64 d; asm("add.rn.f32x2 %0,%1,%2;" : "=l"(d) : "l"(a), "l"(b)); return d;
}
__device__ __forceinline__ u64 splat2(float c) { return pk2(c, c); }

// butterfly step on a packed f32x2: 2 shuffles + 1 packed add
__device__ __forceinline__ u64 shfl_add2(u64 v, int off) {
    float2 s = upk2(v);
    float ax = __shfl_xor_sync(FULLMASK, s.x, off);
    float ay = __shfl_xor_sync(FULLMASK, s.y, off);
    return add2_(v, pk2(ax, ay));
}

// g(r) = r - sin(2*pi*r)/(2*pi), odd Taylor to r^15, valid on [-0.5,0.5]
// (max abs err ~1.3e-7). diff_round(diff_round(x)) = rint(x) + g(g(x - rint(x))).
__device__ __forceinline__ u64 gpoly2(u64 r) {
    u64 z = mul2_(r, r);
    u64 p =            splat2( 0.1142928f);   //  (2pi)^14/15!
    p = fma2_(p, z, splat2(-0.6079655f));     // -(2pi)^12/13!
    p = fma2_(p, z, splat2( 2.4023870f));     //  (2pi)^10/11!
    p = fma2_(p, z, splat2(-6.6938470f));     // -(2pi)^8 / 9!
    p = fma2_(p, z, splat2(12.2081128f));     //  (2pi)^6 / 7!
    p = fma2_(p, z, splat2(-12.9878788f));    // -(2pi)^4 / 5!
    p = fma2_(p, z, splat2( 6.5797363f));     //  (2pi)^2 / 3!
    return mul2_(mul2_(p, z), r);             // r^3 * series(z)
}

__global__ void zero_out_kernel(float* out, int n) {
    int i = blockIdx.x * blockDim.x + threadIdx.x;
    if (i < n) out[i] = 0.0f;
}

// Half-warp per area: 16 lanes x float4 = 64 elements. Warp covers 2 areas.
__global__ __launch_bounds__(256) void area_loss_kernel(
    const float4* __restrict__ img4,
    const float4* __restrict__ msk4,
    float* __restrict__ out,
    int nPairs, float invTotal)
{
    __shared__ float bsum;
    if (threadIdx.x == 0) bsum = 0.0f;
    __syncthreads();

    const int lane = threadIdx.x & 31;
    const int q    = lane & 15;        // lane within half-warp
    const int h    = lane >> 4;        // which half
    const int warpId = (blockIdx.x * blockDim.x + threadIdx.x) >> 5;
    const int nWarps = (gridDim.x * blockDim.x) >> 5;

    float acc = 0.0f;

    for (int w = warpId; w < nPairs; w += nWarps) {
        const int a   = 2 * w + h;
        const int idx = a * 16 + q;
        float4 iv = img4[idx];
        float4 mv = msk4[idx];

        // range reduction (scalar rint), then everything packed
        float n0 = rintf(mv.x), n1 = rintf(mv.y), n2 = rintf(mv.z), n3 = rintf(mv.w);
        u64 r01 = pk2(mv.x - n0, mv.y - n1);
        u64 r23 = pk2(mv.z - n2, mv.w - n3);
        u64 m01 = add2_(gpoly2(gpoly2(r01)), pk2(n0, n1));
        u64 m23 = add2_(gpoly2(gpoly2(r23)), pk2(n2, n3));

        u64 i01 = pk2(iv.x, iv.y), i23 = pk2(iv.z, iv.w);
        u64 t01 = mul2_(i01, m01), t23 = mul2_(i23, m23);

        // joint (sum_m, sum_t) packed reduction across the half-warp
        float2 smp = upk2(add2_(m01, m23));   // partial sum_m over this lane's 4 elems
        float2 stp = upk2(add2_(t01, t23));   // partial sum_t
        u64 red = pk2(smp.x + smp.y, stp.x + stp.y);   // (sum_m, sum_t)
        red = shfl_add2(red, 8);
        red = shfl_add2(red, 4);
        red = shfl_add2(red, 2);
        red = shfl_add2(red, 1);
        float2 sums = upk2(red);              // x = sum_m, y = sum_t

        float rinv = __frcp_rn(sums.x + EPSF);
        float mean = sums.y * rinv;

        u64 nm  = splat2(-mean);
        u64 d01 = mul2_(add2_(t01, nm), m01);
        u64 d23 = mul2_(add2_(t23, nm), m23);
        float2 vp = upk2(fma2_(d01, d01, mul2_(d23, d23)));
        float sv = vp.x + vp.y;
        #pragma unroll
        for (int o = 8; o > 0; o >>= 1)
            sv += __shfl_xor_sync(FULLMASK, sv, o);

        acc = fmaf(sv, rinv, acc);     // identical across each half-warp
    }

    acc += __shfl_xor_sync(FULLMASK, acc, 16);  // combine both halves (uniform in warp)
    if (lane == 0) atomicAdd(&bsum, acc);
    __syncthreads();
    if (threadIdx.x == 0) atomicAdd(out, bsum * invTotal);
}

extern "C" void kernel_launch(void* const* d_in, const int* in_sizes, int n_in,
                              void* d_out, int out_size)
{
    const float4* img4 = (const float4*)d_in[0];  // sv_area_image
    const float4* msk4 = (const float4*)d_in[1];  // sv_area_mask
    float* out = (float*)d_out;

    const int nAreas = in_sizes[0] / 64;          // B*N areas of 8x8
    const int nPairs = nAreas / 2;
    const float invTotal = 1.0f / (float)nAreas;

    zero_out_kernel<<<(out_size + 255) / 256, 256>>>(out, out_size);

    area_loss_kernel<<<1024, 256>>>(img4, msk4, out, nPairs, invTotal);
}

// round 5
// speedup vs baseline: 1.5212x; 1.1165x over previous
#include <cuda_runtime.h>

typedef unsigned long long u64;
#define FULLMASK 0xffffffffu
static constexpr float EPSF = 1e-8f;

// ---------- packed f32x2 helpers (sm_103a) ----------
__device__ __forceinline__ u64 pk2(float lo, float hi) {
    u64 d; asm("mov.b64 %0,{%1,%2};" : "=l"(d) : "f"(lo), "f"(hi)); return d;
}
__device__ __forceinline__ float2 upk2(u64 v) {
    float2 o; asm("mov.b64 {%0,%1},%2;" : "=f"(o.x), "=f"(o.y) : "l"(v)); return o;
}
__device__ __forceinline__ u64 fma2_(u64 a, u64 b, u64 c) {
    u64 d; asm("fma.rn.f32x2 %0,%1,%2,%3;" : "=l"(d) : "l"(a), "l"(b), "l"(c)); return d;
}
__device__ __forceinline__ u64 mul2_(u64 a, u64 b) {
    u64 d; asm("mul.rn.f32x2 %0,%1,%2;" : "=l"(d) : "l"(a), "l"(b)); return d;
}
__device__ __forceinline__ u64 add2_(u64 a, u64 b) {
    u64 d; asm("add.rn.f32x2 %0,%1,%2;" : "=l"(d) : "l"(a), "l"(b)); return d;
}
__device__ __forceinline__ u64 splat2(float c) { return pk2(c, c); }

__device__ __forceinline__ float rcp_approx(float x) {
    float r; asm("rcp.approx.f32 %0, %1;" : "=f"(r) : "f"(x)); return r;
}

// butterfly step on a packed f32x2: 2 shuffles + 1 packed add
__device__ __forceinline__ u64 shfl_add2(u64 v, int off) {
    float2 s = upk2(v);
    float ax = __shfl_xor_sync(FULLMASK, s.x, off);
    float ay = __shfl_xor_sync(FULLMASK, s.y, off);
    return add2_(v, pk2(ax, ay));
}

// g(r) = r - sin(2*pi*r)/(2*pi), odd Taylor to r^11 on [-0.5,0.5]
// (max abs err ~8e-5; after double application ~2e-4 worst case — well
// inside the 1e-3 rel-err budget since typical |r| << 0.5).
// diff_round(diff_round(x)) = rint(x) + g(g(x - rint(x))).
__device__ __forceinline__ u64 gpoly2(u64 r) {
    u64 z = mul2_(r, r);
    u64 p =            splat2(  2.4023870f);  //  (2pi)^10/11!
    p = fma2_(p, z, splat2( -6.6938470f));    // -(2pi)^8 / 9!
    p = fma2_(p, z, splat2( 12.2081128f));    //  (2pi)^6 / 7!
    p = fma2_(p, z, splat2(-12.9878788f));    // -(2pi)^4 / 5!
    p = fma2_(p, z, splat2(  6.5797363f));    //  (2pi)^2 / 3!
    return mul2_(mul2_(p, z), r);             // r * z * series(z)
}

// mask transform for one float4: m = rint(x) + g(g(x - rint(x))), packed pairs
__device__ __forceinline__ void mask2(float4 mv, u64& m01, u64& m23) {
    float n0 = rintf(mv.x), n1 = rintf(mv.y), n2 = rintf(mv.z), n3 = rintf(mv.w);
    u64 r01 = pk2(mv.x - n0, mv.y - n1);
    u64 r23 = pk2(mv.z - n2, mv.w - n3);
    m01 = add2_(gpoly2(gpoly2(r01)), pk2(n0, n1));
    m23 = add2_(gpoly2(gpoly2(r23)), pk2(n2, n3));
}

__global__ void zero_out_kernel(float* out, int n) {
    int i = blockIdx.x * blockDim.x + threadIdx.x;
    if (i < n) out[i] = 0.0f;
}

// 8 lanes per area: each lane holds 8 elements (2 x float4 per array).
// A warp covers 4 areas per iteration; butterflies are 3 steps (offsets 4,2,1).
__global__ __launch_bounds__(256) void area_loss_kernel(
    const float4* __restrict__ img4,
    const float4* __restrict__ msk4,
    float* __restrict__ out,
    int nQuads, float invTotal)
{
    __shared__ float bsum;
    if (threadIdx.x == 0) bsum = 0.0f;
    __syncthreads();

    const int lane = threadIdx.x & 31;
    const int q    = lane & 7;         // lane within octet
    const int oct  = lane >> 3;        // which area of the quad
    const int warpId = (blockIdx.x * blockDim.x + threadIdx.x) >> 5;
    const int nWarps = (gridDim.x * blockDim.x) >> 5;

    float acc = 0.0f;

    #pragma unroll 2
    for (int w = warpId; w < nQuads; w += nWarps) {
        const int a    = 4 * w + oct;
        const int base = a * 16 + q * 2;    // 2 consecutive float4s per lane

        float4 iv0 = img4[base], iv1 = img4[base + 1];
        float4 mv0 = msk4[base], mv1 = msk4[base + 1];

        u64 m01, m23, m45, m67;
        mask2(mv0, m01, m23);
        mask2(mv1, m45, m67);

        u64 t01 = mul2_(pk2(iv0.x, iv0.y), m01);
        u64 t23 = mul2_(pk2(iv0.z, iv0.w), m23);
        u64 t45 = mul2_(pk2(iv1.x, iv1.y), m45);
        u64 t67 = mul2_(pk2(iv1.z, iv1.w), m67);

        // per-lane partials over 8 elements
        float2 pm = upk2(add2_(add2_(m01, m23), add2_(m45, m67)));
        float2 pt = upk2(add2_(add2_(t01, t23), add2_(t45, t67)));

        // joint (sum_m, sum_t) packed butterfly over the octet (3 steps)
        u64 red = pk2(pm.x + pm.y, pt.x + pt.y);
        red = shfl_add2(red, 4);
        red = shfl_add2(red, 2);
        red = shfl_add2(red, 1);
        float2 sums = upk2(red);            // x = sum_m, y = sum_t

        float rinv = rcp_approx(sums.x + EPSF);
        float mean = sums.y * rinv;

        u64 nm  = splat2(-mean);
        u64 d01 = mul2_(add2_(t01, nm), m01);
        u64 d23 = mul2_(add2_(t23, nm), m23);
        u64 d45 = mul2_(add2_(t45, nm), m45);
        u64 d67 = mul2_(add2_(t67, nm), m67);

        u64 v = mul2_(d01, d01);
        v = fma2_(d23, d23, v);
        v = fma2_(d45, d45, v);
        v = fma2_(d67, d67, v);
        float2 vp = upk2(v);
        float sv = vp.x + vp.y;
        sv += __shfl_xor_sync(FULLMASK, sv, 4);
        sv += __shfl_xor_sync(FULLMASK, sv, 2);
        sv += __shfl_xor_sync(FULLMASK, sv, 1);

        acc = fmaf(sv, rinv, acc);          // uniform within each octet
    }

    // combine the 4 octets' accumulators (each octet uniform)
    acc += __shfl_xor_sync(FULLMASK, acc, 8);
    acc += __shfl_xor_sync(FULLMASK, acc, 16);
    if (lane == 0) atomicAdd(&bsum, acc);
    __syncthreads();
    if (threadIdx.x == 0) atomicAdd(out, bsum * invTotal);
}

extern "C" void kernel_launch(void* const* d_in, const int* in_sizes, int n_in,
                              void* d_out, int out_size)
{
    const float4* img4 = (const float4*)d_in[0];  // sv_area_image
    const float4* msk4 = (const float4*)d_in[1];  // sv_area_mask
    float* out = (float*)d_out;

    const int nAreas = in_sizes[0] / 64;          // B*N areas of 8x8
    const int nQuads = nAreas / 4;
    const float invTotal = 1.0f / (float)nAreas;

    zero_out_kernel<<<(out_size + 255) / 256, 256>>>(out, out_size);

    area_loss_kernel<<<1024, 256>>>(img4, msk4, out, nQuads, invTotal);
}

// round 6
// speedup vs baseline: 1.5508x; 1.0194x over previous
#include <cuda_runtime.h>

typedef unsigned long long u64;
#define FULLMASK 0xffffffffu
static constexpr float EPSF = 1e-8f;

// ---------- packed f32x2 helpers (sm_103a) ----------
__device__ __forceinline__ u64 pk2(float lo, float hi) {
    u64 d; asm("mov.b64 %0,{%1,%2};" : "=l"(d) : "f"(lo), "f"(hi)); return d;
}
__device__ __forceinline__ float2 upk2(u64 v) {
    float2 o; asm("mov.b64 {%0,%1},%2;" : "=f"(o.x), "=f"(o.y) : "l"(v)); return o;
}
__device__ __forceinline__ u64 fma2_(u64 a, u64 b, u64 c) {
    u64 d; asm("fma.rn.f32x2 %0,%1,%2,%3;" : "=l"(d) : "l"(a), "l"(b), "l"(c)); return d;
}
__device__ __forceinline__ u64 mul2_(u64 a, u64 b) {
    u64 d; asm("mul.rn.f32x2 %0,%1,%2;" : "=l"(d) : "l"(a), "l"(b)); return d;
}
__device__ __forceinline__ u64 add2_(u64 a, u64 b) {
    u64 d; asm("add.rn.f32x2 %0,%1,%2;" : "=l"(d) : "l"(a), "l"(b)); return d;
}
__device__ __forceinline__ u64 splat2(float c) { return pk2(c, c); }

__device__ __forceinline__ float rcp_approx(float x) {
    float r; asm("rcp.approx.f32 %0, %1;" : "=f"(r) : "f"(x)); return r;
}

// butterfly step on a packed f32x2: 2 shuffles + 1 packed add
__device__ __forceinline__ u64 shfl_add2(u64 v, int off) {
    float2 s = upk2(v);
    float ax = __shfl_xor_sync(FULLMASK, s.x, off);
    float ay = __shfl_xor_sync(FULLMASK, s.y, off);
    return add2_(v, pk2(ax, ay));
}

// g(r) = r - sin(2*pi*r)/(2*pi), odd Taylor to r^11 on [-0.5,0.5].
// diff_round(diff_round(x)) = rint(x) + g(g(x - rint(x))).
__device__ __forceinline__ u64 gpoly2(u64 r) {
    u64 z = mul2_(r, r);
    u64 p =            splat2(  2.4023870f);  //  (2pi)^10/11!
    p = fma2_(p, z, splat2( -6.6938470f));    // -(2pi)^8 / 9!
    p = fma2_(p, z, splat2( 12.2081128f));    //  (2pi)^6 / 7!
    p = fma2_(p, z, splat2(-12.9878788f));    // -(2pi)^4 / 5!
    p = fma2_(p, z, splat2(  6.5797363f));    //  (2pi)^2 / 3!
    return mul2_(mul2_(p, z), r);             // r * z * series(z)
}

// mask transform for one float4: m = rint(x) + g(g(x - rint(x))), packed pairs
__device__ __forceinline__ void mask2(float4 mv, u64& m01, u64& m23) {
    float n0 = rintf(mv.x), n1 = rintf(mv.y), n2 = rintf(mv.z), n3 = rintf(mv.w);
    u64 r01 = pk2(mv.x - n0, mv.y - n1);
    u64 r23 = pk2(mv.z - n2, mv.w - n3);
    m01 = add2_(gpoly2(gpoly2(r01)), pk2(n0, n1));
    m23 = add2_(gpoly2(gpoly2(r23)), pk2(n2, n3));
}

__global__ void zero_out_kernel(float* out, int n) {
    int i = blockIdx.x * blockDim.x + threadIdx.x;
    if (i < n) out[i] = 0.0f;
}

// 8 lanes per area, 8 elems/lane. Single-pass sufficient statistics:
//   Sdev2 = A - 2*mean*B + mean^2*C  with  t = i*m, u = m*t,
//   A = sum(u*u), B = sum(m*u), C = sum(m*m)  (all LINEAR -> stay per-lane).
// Only (sum_m, sum_t) crosses lanes -> one 3-step packed butterfly per area.
__global__ __launch_bounds__(256) void area_loss_kernel(
    const float4* __restrict__ img4,
    const float4* __restrict__ msk4,
    float* __restrict__ out,
    int nQuads, float invTotal)
{
    __shared__ float bsum;
    if (threadIdx.x == 0) bsum = 0.0f;
    __syncthreads();

    const int lane = threadIdx.x & 31;
    const int q    = lane & 7;         // lane within octet
    const int oct  = lane >> 3;        // which area of the quad
    const int warpId = (blockIdx.x * blockDim.x + threadIdx.x) >> 5;
    const int nWarps = (gridDim.x * blockDim.x) >> 5;

    u64 acc2 = 0;                      // packed per-lane accumulator

    #pragma unroll 2
    for (int w = warpId; w < nQuads; w += nWarps) {
        const int a    = 4 * w + oct;
        const int base = a * 16 + q * 2;    // 2 consecutive float4s per lane

        float4 iv0 = img4[base], iv1 = img4[base + 1];
        float4 mv0 = msk4[base], mv1 = msk4[base + 1];

        u64 m01, m23, m45, m67;
        mask2(mv0, m01, m23);
        mask2(mv1, m45, m67);

        u64 t01 = mul2_(pk2(iv0.x, iv0.y), m01);
        u64 t23 = mul2_(pk2(iv0.z, iv0.w), m23);
        u64 t45 = mul2_(pk2(iv1.x, iv1.y), m45);
        u64 t67 = mul2_(pk2(iv1.z, iv1.w), m67);

        u64 u01 = mul2_(m01, t01), u23 = mul2_(m23, t23);
        u64 u45 = mul2_(m45, t45), u67 = mul2_(m67, t67);

        // per-lane linear statistics (no cross-lane reduction needed)
        u64 A2 = mul2_(u01, u01);
        A2 = fma2_(u23, u23, A2); A2 = fma2_(u45, u45, A2); A2 = fma2_(u67, u67, A2);
        u64 B2 = mul2_(m01, u01);
        B2 = fma2_(m23, u23, B2); B2 = fma2_(m45, u45, B2); B2 = fma2_(m67, u67, B2);
        u64 C2 = mul2_(m01, m01);
        C2 = fma2_(m23, m23, C2); C2 = fma2_(m45, m45, C2); C2 = fma2_(m67, m67, C2);

        // only (sum_m, sum_t) crosses lanes: one joint 3-step butterfly
        float2 pm = upk2(add2_(add2_(m01, m23), add2_(m45, m67)));
        float2 pt = upk2(add2_(add2_(t01, t23), add2_(t45, t67)));
        u64 red = pk2(pm.x + pm.y, pt.x + pt.y);
        red = shfl_add2(red, 4);
        red = shfl_add2(red, 2);
        red = shfl_add2(red, 1);
        float2 sums = upk2(red);            // x = sum_m, y = sum_t (uniform/octet)

        float rinv = rcp_approx(sums.x + EPSF);
        float mean = sums.y * rinv;

        // lane contribution: (A - 2*mean*B + mean^2*C) * rinv, fully packed
        u64 w2 = fma2_(splat2(mean), C2, mul2_(splat2(-2.0f), B2)); // mean*C - 2B
        u64 c2 = fma2_(splat2(mean), w2, A2);                       // A + mean*(...)
        acc2 = fma2_(c2, splat2(rinv), acc2);
    }

    // epilogue: collapse packed lanes, full-warp butterfly, one atomic/block
    float2 ap = upk2(acc2);
    float acc = ap.x + ap.y;
    #pragma unroll
    for (int o = 16; o > 0; o >>= 1)
        acc += __shfl_xor_sync(FULLMASK, acc, o);
    if (lane == 0) atomicAdd(&bsum, acc);
    __syncthreads();
    if (threadIdx.x == 0) atomicAdd(out, bsum * invTotal);
}

extern "C" void kernel_launch(void* const* d_in, const int* in_sizes, int n_in,
                              void* d_out, int out_size)
{
    const float4* img4 = (const float4*)d_in[0];  // sv_area_image
    const float4* msk4 = (const float4*)d_in[1];  // sv_area_mask
    float* out = (float*)d_out;

    const int nAreas = in_sizes[0] / 64;          // B*N areas of 8x8
    const int nQuads = nAreas / 4;
    const float invTotal = 1.0f / (float)nAreas;

    zero_out_kernel<<<(out_size + 255) / 256, 256>>>(out, out_size);

    area_loss_kernel<<<1024, 256>>>(img4, msk4, out, nQuads, invTotal);
}

// round 7
// speedup vs baseline: 1.5920x; 1.0266x over previous
#include <cuda_runtime.h>

typedef unsigned long long u64;
#define FULLMASK 0xffffffffu
static constexpr float EPSF = 1e-8f;

// ---------- packed f32x2 helpers (sm_103a) ----------
__device__ __forceinline__ u64 pk2(float lo, float hi) {
    u64 d; asm("mov.b64 %0,{%1,%2};" : "=l"(d) : "f"(lo), "f"(hi)); return d;
}
__device__ __forceinline__ float2 upk2(u64 v) {
    float2 o; asm("mov.b64 {%0,%1},%2;" : "=f"(o.x), "=f"(o.y) : "l"(v)); return o;
}
__device__ __forceinline__ u64 fma2_(u64 a, u64 b, u64 c) {
    u64 d; asm("fma.rn.f32x2 %0,%1,%2,%3;" : "=l"(d) : "l"(a), "l"(b), "l"(c)); return d;
}
__device__ __forceinline__ u64 mul2_(u64 a, u64 b) {
    u64 d; asm("mul.rn.f32x2 %0,%1,%2;" : "=l"(d) : "l"(a), "l"(b)); return d;
}
__device__ __forceinline__ u64 add2_(u64 a, u64 b) {
    u64 d; asm("add.rn.f32x2 %0,%1,%2;" : "=l"(d) : "l"(a), "l"(b)); return d;
}
__device__ __forceinline__ u64 splat2(float c) { return pk2(c, c); }

__device__ __forceinline__ float rcp_approx(float x) {
    float r; asm("rcp.approx.f32 %0, %1;" : "=f"(r) : "f"(x)); return r;
}

// butterfly step on a packed f32x2: 2 shuffles + 1 packed add
__device__ __forceinline__ u64 shfl_add2(u64 v, int off) {
    float2 s = upk2(v);
    float ax = __shfl_xor_sync(FULLMASK, s.x, off);
    float ay = __shfl_xor_sync(FULLMASK, s.y, off);
    return add2_(v, pk2(ax, ay));
}

// g(r) = r - sin(2*pi*r)/(2*pi), odd Taylor to r^11 on [-0.5,0.5].
// diff_round(diff_round(x)) = rint(x) + g(g(x - rint(x))).
__device__ __forceinline__ u64 gpoly2(u64 r) {
    u64 z = mul2_(r, r);
    u64 p =            splat2(  2.4023870f);  //  (2pi)^10/11!
    p = fma2_(p, z, splat2( -6.6938470f));    // -(2pi)^8 / 9!
    p = fma2_(p, z, splat2( 12.2081128f));    //  (2pi)^6 / 7!
    p = fma2_(p, z, splat2(-12.9878788f));    // -(2pi)^4 / 5!
    p = fma2_(p, z, splat2(  6.5797363f));    //  (2pi)^2 / 3!
    return mul2_(mul2_(p, z), r);             // r * z * series(z)
}

// mask transform for one float4: m = rint(x) + g(g(x - rint(x))), packed pairs
__device__ __forceinline__ void mask2(float4 mv, u64& m01, u64& m23) {
    float n0 = rintf(mv.x), n1 = rintf(mv.y), n2 = rintf(mv.z), n3 = rintf(mv.w);
    u64 r01 = pk2(mv.x - n0, mv.y - n1);
    u64 r23 = pk2(mv.z - n2, mv.w - n3);
    m01 = add2_(gpoly2(gpoly2(r01)), pk2(n0, n1));
    m23 = add2_(gpoly2(gpoly2(r23)), pk2(n2, n3));
}

__global__ void zero_out_kernel(float* out, int n) {
    int i = blockIdx.x * blockDim.x + threadIdx.x;
    if (i < n) out[i] = 0.0f;
}

// One quad (4 areas) of work for this lane; accumulates into acc2.
__device__ __forceinline__ void do_quad(
    float4 iv0, float4 iv1, float4 mv0, float4 mv1, u64& acc2)
{
    u64 m01, m23, m45, m67;
    mask2(mv0, m01, m23);
    mask2(mv1, m45, m67);

    u64 t01 = mul2_(pk2(iv0.x, iv0.y), m01);
    u64 t23 = mul2_(pk2(iv0.z, iv0.w), m23);
    u64 t45 = mul2_(pk2(iv1.x, iv1.y), m45);
    u64 t67 = mul2_(pk2(iv1.z, iv1.w), m67);

    u64 u01 = mul2_(m01, t01), u23 = mul2_(m23, t23);
    u64 u45 = mul2_(m45, t45), u67 = mul2_(m67, t67);

    // per-lane linear statistics (stay local; no cross-lane reduction)
    u64 A2 = mul2_(u01, u01);
    A2 = fma2_(u23, u23, A2); A2 = fma2_(u45, u45, A2); A2 = fma2_(u67, u67, A2);
    u64 B2 = mul2_(m01, u01);
    B2 = fma2_(m23, u23, B2); B2 = fma2_(m45, u45, B2); B2 = fma2_(m67, u67, B2);
    u64 C2 = mul2_(m01, m01);
    C2 = fma2_(m23, m23, C2); C2 = fma2_(m45, m45, C2); C2 = fma2_(m67, m67, C2);

    // only (sum_m, sum_t) crosses lanes: one joint 3-step butterfly
    float2 pm = upk2(add2_(add2_(m01, m23), add2_(m45, m67)));
    float2 pt = upk2(add2_(add2_(t01, t23), add2_(t45, t67)));
    u64 red = pk2(pm.x + pm.y, pt.x + pt.y);
    red = shfl_add2(red, 4);
    red = shfl_add2(red, 2);
    red = shfl_add2(red, 1);
    float2 sums = upk2(red);            // x = sum_m, y = sum_t (uniform/octet)

    float rinv = rcp_approx(sums.x + EPSF);
    float mean = sums.y * rinv;

    // lane contribution: (A - 2*mean*B + mean^2*C) * rinv
    u64 w2 = fma2_(splat2(mean), C2, mul2_(splat2(-2.0f), B2));
    u64 c2 = fma2_(splat2(mean), w2, A2);
    acc2 = fma2_(c2, splat2(rinv), acc2);
}

// 8 lanes per area, 8 elems/lane, warp covers 4 areas (one "quad") per unit.
// Chunks of 4 quads: 16 independent LDG.128 front-batched, 4 independent
// poly/butterfly chains interleaved -> hides DRAM + shuffle latency.
__global__ __launch_bounds__(256) void area_loss_kernel(
    const float4* __restrict__ img4,
    const float4* __restrict__ msk4,
    float* __restrict__ out,
    int nQuads, float invTotal)
{
    __shared__ float bsum;
    if (threadIdx.x == 0) bsum = 0.0f;
    __syncthreads();

    const int lane = threadIdx.x & 31;
    const int q    = lane & 7;         // lane within octet
    const int oct  = lane >> 3;        // which area of the quad
    const int warpId = (blockIdx.x * blockDim.x + threadIdx.x) >> 5;
    const int nWarps = (gridDim.x * blockDim.x) >> 5;

    u64 acc2 = 0;                      // packed per-lane accumulator

    int w0 = warpId * 4;
    const int stride = nWarps * 4;

    for (; w0 + 3 < nQuads; w0 += stride) {
        // ---- batched load phase: 16 independent 16B loads ----
        float4 IV[4][2], MV[4][2];
        #pragma unroll
        for (int j = 0; j < 4; j++) {
            const int a    = 4 * (w0 + j) + oct;
            const int base = a * 16 + q * 2;
            IV[j][0] = img4[base];  IV[j][1] = img4[base + 1];
            MV[j][0] = msk4[base];  MV[j][1] = msk4[base + 1];
        }
        // ---- compute phase: 4 independent chains ----
        #pragma unroll
        for (int j = 0; j < 4; j++)
            do_quad(IV[j][0], IV[j][1], MV[j][0], MV[j][1], acc2);
    }
    // tail (not taken for the benchmark shape)
    for (int w = w0; w < nQuads; w++) {
        const int a    = 4 * w + oct;
        const int base = a * 16 + q * 2;
        do_quad(img4[base], img4[base + 1], msk4[base], msk4[base + 1], acc2);
    }

    // epilogue: collapse packed lanes, full-warp butterfly, one atomic/block
    float2 ap = upk2(acc2);
    float acc = ap.x + ap.y;
    #pragma unroll
    for (int o = 16; o > 0; o >>= 1)
        acc += __shfl_xor_sync(FULLMASK, acc, o);
    if (lane == 0) atomicAdd(&bsum, acc);
    __syncthreads();
    if (threadIdx.x == 0) atomicAdd(out, bsum * invTotal);
}

extern "C" void kernel_launch(void* const* d_in, const int* in_sizes, int n_in,
                              void* d_out, int out_size)
{
    const float4* img4 = (const float4*)d_in[0];  // sv_area_image
    const float4* msk4 = (const float4*)d_in[1];  // sv_area_mask
    float* out = (float*)d_out;

    const int nAreas = in_sizes[0] / 64;          // B*N areas of 8x8
    const int nQuads = nAreas / 4;
    const float invTotal = 1.0f / (float)nAreas;

    zero_out_kernel<<<(out_size + 255) / 256, 256>>>(out, out_size);

    area_loss_kernel<<<1024, 256>>>(img4, msk4, out, nQuads, invTotal);
}